// round 8
// baseline (speedup 1.0000x reference)
#include <cuda_runtime.h>
#include <cuda_bf16.h>

#define NN 100000
#define EE 1600000
#define BB 64
#define BNEPS 1e-5f
#define NBLK ((NN + 1023) / 1024)

// g_M layout per layer: M1[din], then M2 rows padded to (din+1)
#define M1OFF 0
#define M2OFF 16
#define M3OFF 304
#define MTOT 1392

// ---------------- scratch ----------------
__device__ __align__(16) float g_P[(size_t)NN * 4];
__device__ __align__(16) __nv_bfloat16 g_Pb[(size_t)NN * 32];
__device__ __align__(16) float g_A[(size_t)NN * 32];
__device__ __align__(16) float g_Y[(size_t)NN * 64];
__device__ __align__(16) int g_degi[NN];
__device__ int g_rowptr[NN + 1];
__device__ int g_cursor[NN];
__device__ int g_src[EE];
__device__ int g_batch[NN];
__device__ float g_dis[NN];
__device__ float g_M[MTOT];
__device__ int g_bsum[NBLK];
__device__ int g_boff[NBLK];
__device__ __align__(16) float g_pool[BB * 64];
__device__ float g_cnt[BB];
__device__ int g_flag;
__device__ int g_done;

__device__ __forceinline__ int detect_e64(const void* ei) {
    const long long* p = (const long long*)ei;
    int ok = 1;
    for (int i = 0; i < 64; i++) {
        long long v = p[i];
        if (v < 0 || v >= NN) ok = 0;
    }
    return ok;
}

// ---------------- hist (degree) ----------------
__global__ void hist_kernel(const void* ei) {
    __shared__ int s64;
    if (threadIdx.x == 0) s64 = detect_e64(ei);
    __syncthreads();
    int e = blockIdx.x * blockDim.x + threadIdx.x;
    if (e >= EE) return;
    int c = s64 ? (int)((const long long*)ei)[EE + e] : ((const int*)ei)[EE + e];
    atomicAdd(&g_degi[c], 1);
}

// ---------------- scan phase 1 (+ batch decode) ----------------
__global__ void scan1_kernel(const void* batch) {
    __shared__ int s[256];
    __shared__ int s64b;
    int t = threadIdx.x;
    if (t == 0) {
        const long long* q = (const long long*)batch;
        int okb = 1;
        for (int i = 0; i < 32; i++) {
            long long v = q[NN / 4 + i];
            if (v < 0 || v >= BB) okb = 0;
        }
        s64b = okb;
    }
    int base = blockIdx.x * 1024 + t * 4;
    int sum = 0;
    if (base + 3 < NN) {
        int4 d = *(const int4*)&g_degi[base];
        sum = d.x + d.y + d.z + d.w;
    } else {
        for (int u = 0; u < 4; u++) if (base + u < NN) sum += g_degi[base + u];
    }
    s[t] = sum;
    __syncthreads();
    for (int off = 128; off > 0; off >>= 1) {
        if (t < off) s[t] += s[t + off];
        __syncthreads();
    }
    if (t == 0) g_bsum[blockIdx.x] = s[0];
    int nt = gridDim.x * blockDim.x;
    int b64 = s64b;
    for (int i = blockIdx.x * blockDim.x + t; i < NN; i += nt)
        g_batch[i] = b64 ? (int)((const long long*)batch)[i] : ((const int*)batch)[i];
}

// ---------------- merged scan2+scan3 (+ zero pool/cnt/M) ----------------
__global__ void scan23_kernel() {
    int t = threadIdx.x;
    int bid = blockIdx.x;
    __shared__ int s2[128];
    if (bid == 0) {
        int v = 0;
        if (t < 128) { v = (t < NBLK) ? g_bsum[t] : 0; s2[t] = v; }
        __syncthreads();
        for (int off = 1; off < 128; off <<= 1) {
            int u = (t < 128 && t >= off) ? s2[t - off] : 0;
            __syncthreads();
            if (t < 128) s2[t] += u;
            __syncthreads();
        }
        if (t < NBLK) g_boff[t] = s2[t] - v;
        if (t == 127) g_rowptr[NN] = s2[127];
        __threadfence();
        __syncthreads();
        if (t == 0) g_flag = 1;
        for (int u = t; u < BB * 64; u += 256) g_pool[u] = 0.0f;
        if (t < BB) g_cnt[t] = 0.0f;
        for (int u = t; u < MTOT; u += 256) g_M[u] = 0.0f;
    } else {
        if (t == 0) { while (((volatile int*)&g_flag)[0] == 0) {} }
        __syncthreads();
    }
    // ---- scan3 body ----
    __shared__ int s3[256];
    int base = bid * 1024 + t * 4;
    int d0 = 0, d1 = 0, d2 = 0, d3 = 0;
    if (base + 3 < NN) {
        int4 d = *(const int4*)&g_degi[base];
        d0 = d.x; d1 = d.y; d2 = d.z; d3 = d.w;
    } else {
        if (base + 0 < NN) d0 = g_degi[base + 0];
        if (base + 1 < NN) d1 = g_degi[base + 1];
        if (base + 2 < NN) d2 = g_degi[base + 2];
        if (base + 3 < NN) d3 = g_degi[base + 3];
    }
    int tsum = d0 + d1 + d2 + d3;
    s3[t] = tsum;
    __syncthreads();
    for (int off = 1; off < 256; off <<= 1) {
        int u = (t >= off) ? s3[t - off] : 0;
        __syncthreads();
        s3[t] += u;
        __syncthreads();
    }
    int off = g_boff[bid] + s3[t] - tsum;
    int pre[4] = {off, off + d0, off + d0 + d1, off + d0 + d1 + d2};
    int dd[4] = {d0, d1, d2, d3};
    for (int u = 0; u < 4; u++) {
        int idx = base + u;
        if (idx < NN) {
            g_rowptr[idx] = pre[u];
            g_cursor[idx] = pre[u];
            g_dis[idx] = rsqrtf((float)(dd[u] + 1));
        }
    }
    // reset flag for next graph replay (last block)
    __syncthreads();
    if (t == 0) {
        int d = atomicAdd(&g_done, 1);
        if (d == (int)gridDim.x - 1) { g_done = 0; g_flag = 0; __threadfence(); }
    }
}

// ---------------- fill CSR + prep layer-1 messages ----------------
__global__ void fillprep_kernel(const void* ei, const float* __restrict__ x) {
    __shared__ int s64;
    if (threadIdx.x == 0) s64 = detect_e64(ei);
    __syncthreads();
    int e = blockIdx.x * blockDim.x + threadIdx.x;
    if (e < EE) {
        int r, c;
        if (s64) {
            const long long* p = (const long long*)ei;
            r = (int)p[e]; c = (int)p[EE + e];
        } else {
            const int* p = (const int*)ei;
            r = p[e]; c = p[EE + e];
        }
        int pos = atomicAdd(&g_cursor[c], 1);
        g_src[pos] = r;
    }
    if (e < NN) {
        float d = g_dis[e];
        ((float4*)g_P)[e] = make_float4(x[3 * e] * d, x[3 * e + 1] * d, x[3 * e + 2] * d, 0.0f);
    }
}

// ---------------- layer-1 gather (fp32 float4) + inline moments ----------------
__global__ void gather1m_kernel() {
    int i = blockIdx.x * blockDim.x + threadIdx.x;
    bool valid = (i < NN);
    float4 acc = make_float4(0, 0, 0, 0);
    float d = 0.0f;
    if (valid) {
        const float4* P4 = (const float4*)g_P;
        acc = P4[i];
        int s = g_rowptr[i], e = g_rowptr[i + 1];
        int j = s;
        for (; j + 2 <= e; j += 2) {
            int r0 = g_src[j], r1 = g_src[j + 1];
            float4 v0 = P4[r0];
            float4 v1 = P4[r1];
            acc.x += v0.x + v1.x; acc.y += v0.y + v1.y;
            acc.z += v0.z + v1.z; acc.w += v0.w + v1.w;
        }
        if (j < e) {
            float4 v = P4[g_src[j]];
            acc.x += v.x; acc.y += v.y; acc.z += v.z; acc.w += v.w;
        }
        ((float4*)g_A)[i] = acc;
        d = g_dis[i];
    }
    // inline moments (scaled by dis)
    float s0 = acc.x * d, s1 = acc.y * d, s2 = acc.z * d;
    float m[12];
    m[0] = s0; m[1] = s1; m[2] = s2;
    m[3] = s0 * s0; m[4] = s0 * s1; m[5] = s0 * s2;
    m[6] = s1 * s0; m[7] = s1 * s1; m[8] = s1 * s2;
    m[9] = s2 * s0; m[10] = s2 * s1; m[11] = s2 * s2;
#pragma unroll
    for (int u = 0; u < 12; u++)
        for (int o = 16; o > 0; o >>= 1)
            m[u] += __shfl_down_sync(0xffffffffu, m[u], o);
    if ((threadIdx.x & 31) == 0) {
#pragma unroll
        for (int u = 0; u < 3; u++) atomicAdd(&g_M[M1OFF + u], m[u]);
#pragma unroll
        for (int u = 0; u < 9; u++)
            atomicAdd(&g_M[M1OFF + 3 + (u / 3) * 4 + (u % 3)], m[3 + u]);
    }
}

// ---------------- bf16 gather (CH channels, 8 per thread), unrolled ----------------
template <int CH>
__global__ void gather_bf16_kernel() {
    constexpr int TPN = CH / 8;
    int idx = blockIdx.x * blockDim.x + threadIdx.x;
    if (idx >= NN * TPN) return;
    int i = idx / TPN;
    int sub = idx % TPN;
    const uint4* Pb = (const uint4*)g_Pb;
    float acc[8];
    {
        uint4 v = Pb[(size_t)i * TPN + sub];
        const __nv_bfloat162* h = (const __nv_bfloat162*)&v;
#pragma unroll
        for (int u = 0; u < 4; u++) {
            float2 f = __bfloat1622float2(h[u]);
            acc[2 * u] = f.x; acc[2 * u + 1] = f.y;
        }
    }
    int s = g_rowptr[i], e = g_rowptr[i + 1];
    int j = s;
    for (; j + 2 <= e; j += 2) {
        int r0 = g_src[j], r1 = g_src[j + 1];
        uint4 va = Pb[(size_t)r0 * TPN + sub];
        uint4 vb = Pb[(size_t)r1 * TPN + sub];
        const __nv_bfloat162* ha = (const __nv_bfloat162*)&va;
        const __nv_bfloat162* hb = (const __nv_bfloat162*)&vb;
#pragma unroll
        for (int u = 0; u < 4; u++) {
            float2 fa = __bfloat1622float2(ha[u]);
            float2 fb = __bfloat1622float2(hb[u]);
            acc[2 * u] += fa.x + fb.x;
            acc[2 * u + 1] += fa.y + fb.y;
        }
    }
    if (j < e) {
        uint4 v = Pb[(size_t)g_src[j] * TPN + sub];
        const __nv_bfloat162* h = (const __nv_bfloat162*)&v;
#pragma unroll
        for (int u = 0; u < 4; u++) {
            float2 f = __bfloat1622float2(h[u]);
            acc[2 * u] += f.x; acc[2 * u + 1] += f.y;
        }
    }
    float4* Ao = (float4*)(g_A + (size_t)i * CH + sub * 8);
    Ao[0] = make_float4(acc[0], acc[1], acc[2], acc[3]);
    Ao[1] = make_float4(acc[4], acc[5], acc[6], acc[7]);
}

// ---------------- moments din=16/32 via warp shuffles ----------------
template <int DIN, int MOFF>
__global__ void mom_warp_kernel() {
    constexpr int RPW = 32 / DIN;
    constexpr int NIT = DIN + DIN * (DIN + 1);
    __shared__ float Msh[NIT];
    int t = threadIdx.x;
    for (int u = t; u < NIT; u += 256) Msh[u] = 0.0f;
    __syncthreads();
    int lane = t & 31, w = t >> 5;
    int gw = blockIdx.x * 8 + w;
    int sub = lane / DIN;
    int ch = lane % DIN;
    float acc1 = 0.0f;
    float acc2[DIN];
#pragma unroll
    for (int k = 0; k < DIN; k++) acc2[k] = 0.0f;
    int stride = gridDim.x * 8 * RPW;
    for (int r0 = gw * RPW; r0 < NN; r0 += stride) {
        int r = r0 + sub;
        float s = g_A[(size_t)r * DIN + ch] * g_dis[r];
        acc1 += s;
#pragma unroll
        for (int k = 0; k < DIN; k++)
            acc2[k] += s * __shfl_sync(0xffffffffu, s, k, DIN);
    }
    atomicAdd(&Msh[ch], acc1);
#pragma unroll
    for (int k = 0; k < DIN; k++)
        atomicAdd(&Msh[DIN + ch * (DIN + 1) + k], acc2[k]);
    __syncthreads();
    for (int u = t; u < NIT; u += 256) atomicAdd(&g_M[MOFF + u], Msh[u]);
}

// ---------------- fused: stats-from-moments + h=relu(bn(dis*(A@W)+b)) ----------------
__global__ void fused_out_kernel(const float* __restrict__ A, const float* __restrict__ W,
                                 const float* __restrict__ bias, const float* __restrict__ gam,
                                 const float* __restrict__ bet,
                                 int moff, int din, int astride, int dout, int ld, int to_bf16) {
    extern __shared__ float sh[];
    float* Wsh = sh;                              // astride*dout
    float* Msh = Wsh + astride * dout;            // din + din*(din+1)
    int nM = din + din * (din + 1);
    float* scl = Msh + nM;                        // 64
    float* offs = scl + 64;                       // 64
    int t = threadIdx.x;
    for (int u = t; u < astride * dout; u += blockDim.x)
        Wsh[u] = (u < din * dout) ? W[u] : 0.0f;
    for (int u = t; u < nM; u += blockDim.x) Msh[u] = g_M[moff + u];
    __syncthreads();
    if (t < dout) {
        float m1w = 0.0f;
        for (int k = 0; k < din; k++) m1w += Msh[k] * Wsh[k * dout + t];
        float q = 0.0f;
        for (int j = 0; j < din; j++) {
            float wj = Wsh[j * dout + t];
            const float* mrow = &Msh[din + j * (din + 1)];
            for (int k = 0; k < din; k++) q += wj * mrow[k] * Wsh[k * dout + t];
        }
        float bc = bias[t];
        const float inv_n = 1.0f / NN;
        float mu  = m1w * inv_n + bc;
        float ex2 = q * inv_n + 2.0f * bc * m1w * inv_n + bc * bc;
        float var = ex2 - mu * mu;
        float scale = gam[t] * rsqrtf(var + BNEPS);
        scl[t] = scale;
        offs[t] = (bc - mu) * scale + bet[t];
    }
    __syncthreads();
    int c = t & (dout - 1);
    float scale = scl[c];
    float off = offs[c];
    int rpb = 256 >> ld;
    int rstart = blockIdx.x * rpb + (t >> ld);
    int rstride = gridDim.x * rpb;
    int nk4 = astride >> 2;
    for (int i = rstart; i < NN; i += rstride) {
        const float4* a4 = (const float4*)(A + (size_t)i * astride);
        float dot = 0.0f;
        for (int kk = 0; kk < nk4; kk++) {
            float4 av = a4[kk];
            int kb = kk * 4;
            dot += av.x * Wsh[(kb + 0) * dout + c];
            dot += av.y * Wsh[(kb + 1) * dout + c];
            dot += av.z * Wsh[(kb + 2) * dout + c];
            dot += av.w * Wsh[(kb + 3) * dout + c];
        }
        float d = g_dis[i];
        float h = fmaxf(d * dot * scale + off, 0.0f);
        if (to_bf16) g_Pb[(size_t)i * dout + c] = __float2bfloat16(h * d);
        else g_Y[(size_t)i * dout + c] = h;
    }
}

// ---------------- pooling + FC ----------------
__global__ void pool_kernel() {
    int idx = blockIdx.x * blockDim.x + threadIdx.x;
    if (idx >= NN * 16) return;
    int i = idx >> 4;
    int b = g_batch[i];
    float4 v = ((const float4*)g_Y)[idx];
    float* dst = g_pool + (size_t)b * 64 + (idx & 15) * 4;
    unsigned long long p = (unsigned long long)__cvta_generic_to_global(dst);
    asm volatile("red.global.add.v4.f32 [%0], {%1,%2,%3,%4};"
                 :: "l"(p), "f"(v.x), "f"(v.y), "f"(v.z), "f"(v.w) : "memory");
    if ((idx & 15) == 0) atomicAdd(&g_cnt[b], 1.0f);
}

__global__ void fc_kernel(const float* __restrict__ fcW, const float* __restrict__ fcb,
                          float* __restrict__ out) {
    int t = blockIdx.x * blockDim.x + threadIdx.x;
    if (t >= BB * 10) return;
    int b = t / 10;
    int k = t % 10;
    float cnt = fmaxf(g_cnt[b], 1.0f);
    float s = 0.0f;
    for (int j = 0; j < 64; j++) s += g_pool[b * 64 + j] * fcW[j * 10 + k];
    out[t] = s / cnt + fcb[k];
}

extern "C" void kernel_launch(void* const* d_in, const int* in_sizes, int n_in,
                              void* d_out, int out_size) {
    const float* x     = (const float*)d_in[0];
    const void*  ei    = d_in[1];
    const void*  batch = d_in[2];
    const float* W1 = (const float*)d_in[3];
    const float* b1 = (const float*)d_in[4];
    const float* g1 = (const float*)d_in[5];
    const float* be1 = (const float*)d_in[6];
    const float* W2 = (const float*)d_in[7];
    const float* b2 = (const float*)d_in[8];
    const float* g2 = (const float*)d_in[9];
    const float* be2 = (const float*)d_in[10];
    const float* W3 = (const float*)d_in[11];
    const float* b3 = (const float*)d_in[12];
    const float* g3 = (const float*)d_in[13];
    const float* be3 = (const float*)d_in[14];
    const float* fcW = (const float*)d_in[15];
    const float* fcb = (const float*)d_in[16];
    float* out = (float*)d_out;

    float* Ap;
    int* degp;
    cudaGetSymbolAddress((void**)&Ap, g_A);
    cudaGetSymbolAddress((void**)&degp, g_degi);

    // ---- CSR build ----
    cudaMemsetAsync(degp, 0, NN * sizeof(int));
    hist_kernel<<<(EE + 255) / 256, 256>>>(ei);                 // launch 0
    scan1_kernel<<<NBLK, 256>>>(batch);                          // launch 1
    scan23_kernel<<<NBLK, 256>>>();                              // launch 2
    fillprep_kernel<<<(EE + 255) / 256, 256>>>(ei, x);           // launch 3 (profiled)

    // ---- layer 1 (3->16) ----
    gather1m_kernel<<<(NN + 127) / 128, 128>>>();
    fused_out_kernel<<<1024, 256, (4 * 16 + 16 + 128) * sizeof(float)>>>(
        Ap, W1, b1, g1, be1, M1OFF, 3, 4, 16, 4, 1);

    // ---- layer 2 (16->32) ----
    gather_bf16_kernel<16><<<(NN * 2 + 127) / 128, 128>>>();
    mom_warp_kernel<16, M2OFF><<<128, 256>>>();
    fused_out_kernel<<<1024, 256, (16 * 32 + 288 + 128) * sizeof(float)>>>(
        Ap, W2, b2, g2, be2, M2OFF, 16, 16, 32, 5, 1);

    // ---- layer 3 (32->64) ----
    gather_bf16_kernel<32><<<(NN * 4 + 127) / 128, 128>>>();
    mom_warp_kernel<32, M3OFF><<<128, 256>>>();
    fused_out_kernel<<<1024, 256, (32 * 64 + 1088 + 128) * sizeof(float)>>>(
        Ap, W3, b3, g3, be3, M3OFF, 32, 32, 64, 6, 0);

    // ---- pooling + FC ----
    pool_kernel<<<(NN * 16 + 255) / 256, 256>>>();
    fc_kernel<<<(BB * 10 + 255) / 256, 256>>>(fcW, fcb, out);
}

// round 9
// speedup vs baseline: 1.1028x; 1.1028x over previous
#include <cuda_runtime.h>
#include <cuda_bf16.h>

#define NN 100000
#define EE 1600000
#define BB 64
#define BNEPS 1e-5f
#define NBLK ((NN + 1023) / 1024)

// g_M layout per layer: M1[din], then M2 rows padded to (din+1)
#define M1OFF 0
#define M2OFF 16
#define M3OFF 304
#define MTOT 1392

// ---------------- scratch ----------------
__device__ __align__(16) float g_P[(size_t)NN * 4];
__device__ __align__(16) __nv_bfloat16 g_Pb[(size_t)NN * 32];
__device__ __align__(16) float g_A[(size_t)NN * 32];
__device__ __align__(16) float g_Y[(size_t)NN * 64];
__device__ __align__(16) int g_degi[NN];
__device__ int g_rowptr[NN + 1];
__device__ int g_cursor[NN];
__device__ int g_src[EE];
__device__ int g_batch[NN];
__device__ float g_dis[NN];
__device__ float g_stats[128];
__device__ float g_M[MTOT];
__device__ int g_bsum[NBLK];
__device__ int g_boff[NBLK];
__device__ __align__(16) float g_pool[BB * 64];
__device__ float g_cnt[BB];

__device__ __forceinline__ int detect_e64(const void* ei) {
    const long long* p = (const long long*)ei;
    int ok = 1;
    for (int i = 0; i < 64; i++) {
        long long v = p[i];
        if (v < 0 || v >= NN) ok = 0;
    }
    return ok;
}

// ---------------- hist (degree) ----------------
__global__ void hist_kernel(const void* ei) {
    __shared__ int s64;
    if (threadIdx.x == 0) s64 = detect_e64(ei);
    __syncthreads();
    int e = blockIdx.x * blockDim.x + threadIdx.x;
    if (e >= EE) return;
    int c = s64 ? (int)((const long long*)ei)[EE + e] : ((const int*)ei)[EE + e];
    atomicAdd(&g_degi[c], 1);
}

// ---------------- scan phase 1 (+ batch decode) ----------------
__global__ void scan1_kernel(const void* batch) {
    __shared__ int s[256];
    __shared__ int s64b;
    int t = threadIdx.x;
    if (t == 0) {
        const long long* q = (const long long*)batch;
        int okb = 1;
        for (int i = 0; i < 32; i++) {
            long long v = q[NN / 4 + i];
            if (v < 0 || v >= BB) okb = 0;
        }
        s64b = okb;
    }
    int base = blockIdx.x * 1024 + t * 4;
    int sum = 0;
    if (base + 3 < NN) {
        int4 d = *(const int4*)&g_degi[base];
        sum = d.x + d.y + d.z + d.w;
    } else {
        for (int u = 0; u < 4; u++) if (base + u < NN) sum += g_degi[base + u];
    }
    s[t] = sum;
    __syncthreads();
    for (int off = 128; off > 0; off >>= 1) {
        if (t < off) s[t] += s[t + off];
        __syncthreads();
    }
    if (t == 0) g_bsum[blockIdx.x] = s[0];
    int nt = gridDim.x * blockDim.x;
    int b64 = s64b;
    for (int i = blockIdx.x * blockDim.x + t; i < NN; i += nt)
        g_batch[i] = b64 ? (int)((const long long*)batch)[i] : ((const int*)batch)[i];
}

// ---------------- scan phase 2 (+ zero pool/cnt/M) ----------------
__global__ void scan2_kernel() {
    __shared__ int s[128];
    int t = threadIdx.x;
    int v = (t < NBLK) ? g_bsum[t] : 0;
    s[t] = v;
    __syncthreads();
    for (int off = 1; off < 128; off <<= 1) {
        int u = (t >= off) ? s[t - off] : 0;
        __syncthreads();
        s[t] += u;
        __syncthreads();
    }
    if (t < NBLK) g_boff[t] = s[t] - v;
    if (t == 127) g_rowptr[NN] = s[127];
    for (int u = t; u < BB * 64; u += 128) g_pool[u] = 0.0f;
    if (t < BB) g_cnt[t] = 0.0f;
    for (int u = t; u < MTOT; u += 128) g_M[u] = 0.0f;
}

// ---------------- scan phase 3 ----------------
__global__ void scan3_kernel() {
    __shared__ int s[256];
    int t = threadIdx.x;
    int base = blockIdx.x * 1024 + t * 4;
    int d0 = 0, d1 = 0, d2 = 0, d3 = 0;
    if (base + 3 < NN) {
        int4 d = *(const int4*)&g_degi[base];
        d0 = d.x; d1 = d.y; d2 = d.z; d3 = d.w;
    } else {
        if (base + 0 < NN) d0 = g_degi[base + 0];
        if (base + 1 < NN) d1 = g_degi[base + 1];
        if (base + 2 < NN) d2 = g_degi[base + 2];
        if (base + 3 < NN) d3 = g_degi[base + 3];
    }
    int tsum = d0 + d1 + d2 + d3;
    s[t] = tsum;
    __syncthreads();
    for (int off = 1; off < 256; off <<= 1) {
        int u = (t >= off) ? s[t - off] : 0;
        __syncthreads();
        s[t] += u;
        __syncthreads();
    }
    int off = g_boff[blockIdx.x] + s[t] - tsum;
    int pre[4] = {off, off + d0, off + d0 + d1, off + d0 + d1 + d2};
    int dd[4] = {d0, d1, d2, d3};
    for (int u = 0; u < 4; u++) {
        int idx = base + u;
        if (idx < NN) {
            g_rowptr[idx] = pre[u];
            g_cursor[idx] = pre[u];
            g_dis[idx] = rsqrtf((float)(dd[u] + 1));
        }
    }
}

// ---------------- fill CSR + prep layer-1 messages ----------------
__global__ void fillprep_kernel(const void* ei, const float* __restrict__ x) {
    __shared__ int s64;
    if (threadIdx.x == 0) s64 = detect_e64(ei);
    __syncthreads();
    int e = blockIdx.x * blockDim.x + threadIdx.x;
    if (e < EE) {
        int r, c;
        if (s64) {
            const long long* p = (const long long*)ei;
            r = (int)p[e]; c = (int)p[EE + e];
        } else {
            const int* p = (const int*)ei;
            r = p[e]; c = p[EE + e];
        }
        int pos = atomicAdd(&g_cursor[c], 1);
        g_src[pos] = r;
    }
    if (e < NN) {
        float d = g_dis[e];
        ((float4*)g_P)[e] = make_float4(x[3 * e] * d, x[3 * e + 1] * d, x[3 * e + 2] * d, 0.0f);
    }
}

// ---------------- layer-1 gather (fp32 float4), unroll-4 prefetch ----------------
__global__ void gather1_kernel() {
    int i = blockIdx.x * blockDim.x + threadIdx.x;
    if (i >= NN) return;
    const float4* __restrict__ P4 = (const float4*)g_P;
    float4 acc = P4[i];
    int s = g_rowptr[i], e = g_rowptr[i + 1];
    int j = s;
    for (; j + 4 <= e; j += 4) {
        int r0 = g_src[j], r1 = g_src[j + 1], r2 = g_src[j + 2], r3 = g_src[j + 3];
        float4 v0 = P4[r0];
        float4 v1 = P4[r1];
        float4 v2 = P4[r2];
        float4 v3 = P4[r3];
        acc.x += (v0.x + v1.x) + (v2.x + v3.x);
        acc.y += (v0.y + v1.y) + (v2.y + v3.y);
        acc.z += (v0.z + v1.z) + (v2.z + v3.z);
        acc.w += (v0.w + v1.w) + (v2.w + v3.w);
    }
    for (; j < e; j++) {
        float4 v = P4[g_src[j]];
        acc.x += v.x; acc.y += v.y; acc.z += v.z; acc.w += v.w;
    }
    ((float4*)g_A)[i] = acc;
}

// ---------------- bf16 gather (CH channels, 8 per thread), unroll-4 prefetch ----------------
template <int CH>
__global__ void gather_bf16_kernel() {
    constexpr int TPN = CH / 8;
    int idx = blockIdx.x * blockDim.x + threadIdx.x;
    if (idx >= NN * TPN) return;
    int i = idx / TPN;
    int sub = idx % TPN;
    const uint4* __restrict__ Pb = (const uint4*)g_Pb;
    float acc[8];
    {
        uint4 v = Pb[(size_t)i * TPN + sub];
        const __nv_bfloat162* h = (const __nv_bfloat162*)&v;
#pragma unroll
        for (int u = 0; u < 4; u++) {
            float2 f = __bfloat1622float2(h[u]);
            acc[2 * u] = f.x; acc[2 * u + 1] = f.y;
        }
    }
    int s = g_rowptr[i], e = g_rowptr[i + 1];
    int j = s;
    for (; j + 4 <= e; j += 4) {
        int r0 = g_src[j], r1 = g_src[j + 1], r2 = g_src[j + 2], r3 = g_src[j + 3];
        uint4 v0 = Pb[(size_t)r0 * TPN + sub];
        uint4 v1 = Pb[(size_t)r1 * TPN + sub];
        uint4 v2 = Pb[(size_t)r2 * TPN + sub];
        uint4 v3 = Pb[(size_t)r3 * TPN + sub];
        const __nv_bfloat162* h0 = (const __nv_bfloat162*)&v0;
        const __nv_bfloat162* h1 = (const __nv_bfloat162*)&v1;
        const __nv_bfloat162* h2 = (const __nv_bfloat162*)&v2;
        const __nv_bfloat162* h3 = (const __nv_bfloat162*)&v3;
#pragma unroll
        for (int u = 0; u < 4; u++) {
            float2 f0 = __bfloat1622float2(h0[u]);
            float2 f1 = __bfloat1622float2(h1[u]);
            float2 f2 = __bfloat1622float2(h2[u]);
            float2 f3 = __bfloat1622float2(h3[u]);
            acc[2 * u]     += (f0.x + f1.x) + (f2.x + f3.x);
            acc[2 * u + 1] += (f0.y + f1.y) + (f2.y + f3.y);
        }
    }
    for (; j < e; j++) {
        uint4 v = Pb[(size_t)g_src[j] * TPN + sub];
        const __nv_bfloat162* h = (const __nv_bfloat162*)&v;
#pragma unroll
        for (int u = 0; u < 4; u++) {
            float2 f = __bfloat1622float2(h[u]);
            acc[2 * u] += f.x; acc[2 * u + 1] += f.y;
        }
    }
    float4* Ao = (float4*)(g_A + (size_t)i * CH + sub * 8);
    Ao[0] = make_float4(acc[0], acc[1], acc[2], acc[3]);
    Ao[1] = make_float4(acc[4], acc[5], acc[6], acc[7]);
}

// ---------------- moments din=3 (A astride 4) ----------------
__global__ void mom3_kernel() {
    __shared__ float Msh[12];
    int t = threadIdx.x;
    if (t < 12) Msh[t] = 0.0f;
    __syncthreads();
    float a1[3] = {0, 0, 0};
    float a2[9] = {0, 0, 0, 0, 0, 0, 0, 0, 0};
    int nt = gridDim.x * blockDim.x;
    for (int i = blockIdx.x * blockDim.x + t; i < NN; i += nt) {
        float4 v = ((const float4*)g_A)[i];
        float d = g_dis[i];
        float s0 = v.x * d, s1 = v.y * d, s2 = v.z * d;
        a1[0] += s0; a1[1] += s1; a1[2] += s2;
        a2[0] += s0 * s0; a2[1] += s0 * s1; a2[2] += s0 * s2;
        a2[3] += s1 * s0; a2[4] += s1 * s1; a2[5] += s1 * s2;
        a2[6] += s2 * s0; a2[7] += s2 * s1; a2[8] += s2 * s2;
    }
#pragma unroll
    for (int u = 0; u < 3; u++)
        for (int o = 16; o > 0; o >>= 1) a1[u] += __shfl_down_sync(0xffffffffu, a1[u], o);
#pragma unroll
    for (int u = 0; u < 9; u++)
        for (int o = 16; o > 0; o >>= 1) a2[u] += __shfl_down_sync(0xffffffffu, a2[u], o);
    if ((t & 31) == 0) {
        for (int u = 0; u < 3; u++) atomicAdd(&Msh[u], a1[u]);
        for (int u = 0; u < 9; u++) atomicAdd(&Msh[3 + u], a2[u]);
    }
    __syncthreads();
    if (t < 3) atomicAdd(&g_M[M1OFF + t], Msh[t]);
    if (t >= 3 && t < 12) {
        int u = t - 3;
        atomicAdd(&g_M[M1OFF + 3 + (u / 3) * 4 + (u % 3)], Msh[3 + u]);
    }
}

// ---------------- moments din=16/32 via warp shuffles ----------------
template <int DIN, int MOFF>
__global__ void mom_warp_kernel() {
    constexpr int RPW = 32 / DIN;
    constexpr int NIT = DIN + DIN * (DIN + 1);
    __shared__ float Msh[NIT];
    int t = threadIdx.x;
    for (int u = t; u < NIT; u += 256) Msh[u] = 0.0f;
    __syncthreads();
    int lane = t & 31, w = t >> 5;
    int gw = blockIdx.x * 8 + w;
    int sub = lane / DIN;
    int ch = lane % DIN;
    float acc1 = 0.0f;
    float acc2[DIN];
#pragma unroll
    for (int k = 0; k < DIN; k++) acc2[k] = 0.0f;
    int stride = gridDim.x * 8 * RPW;
    for (int r0 = gw * RPW; r0 < NN; r0 += stride) {
        int r = r0 + sub;
        float s = g_A[(size_t)r * DIN + ch] * g_dis[r];
        acc1 += s;
#pragma unroll
        for (int k = 0; k < DIN; k++)
            acc2[k] += s * __shfl_sync(0xffffffffu, s, k, DIN);
    }
    atomicAdd(&Msh[ch], acc1);
#pragma unroll
    for (int k = 0; k < DIN; k++)
        atomicAdd(&Msh[DIN + ch * (DIN + 1) + k], acc2[k]);
    __syncthreads();
    for (int u = t; u < NIT; u += 256) atomicAdd(&g_M[MOFF + u], Msh[u]);
}

// ---------------- solve BN affine from moments ----------------
__global__ void solve_kernel(const float* __restrict__ W, const float* __restrict__ bias,
                             const float* __restrict__ g, const float* __restrict__ be,
                             int moff, int din, int dout) {
    extern __shared__ float Wsh[];
    for (int u = threadIdx.x; u < din * dout; u += blockDim.x) Wsh[u] = W[u];
    __syncthreads();
    int c = threadIdx.x;
    if (c >= dout) return;
    float m1w = 0.0f;
    for (int k = 0; k < din; k++) m1w += g_M[moff + k] * Wsh[k * dout + c];
    float q = 0.0f;
    for (int j = 0; j < din; j++) {
        float wj = Wsh[j * dout + c];
        const float* mrow = &g_M[moff + din + j * (din + 1)];
        for (int k = 0; k < din; k++) q += wj * mrow[k] * Wsh[k * dout + c];
    }
    float bc = bias[c];
    const float inv_n = 1.0f / NN;
    float mu  = m1w * inv_n + bc;
    float ex2 = q * inv_n + 2.0f * bc * m1w * inv_n + bc * bc;
    float var = ex2 - mu * mu;
    float scale = g[c] * rsqrtf(var + BNEPS);
    float off = (bc - mu) * scale + be[c];
    g_stats[c] = scale;
    g_stats[64 + c] = off;
}

// ---------------- fused: h = relu(bn(dis*(A@W)+b)); write bf16 P or fp32 Y ----------------
__global__ void fused_out_kernel(const float* __restrict__ A, const float* __restrict__ W,
                                 int din, int astride, int dout, int ld, int to_bf16) {
    extern __shared__ float Wsh[];
    for (int u = threadIdx.x; u < astride * dout; u += blockDim.x)
        Wsh[u] = (u < din * dout) ? W[u] : 0.0f;
    __syncthreads();
    int t = threadIdx.x;
    int c = t & (dout - 1);
    float scale = g_stats[c];
    float off = g_stats[64 + c];
    int rpb = 256 >> ld;
    int rstart = blockIdx.x * rpb + (t >> ld);
    int rstride = gridDim.x * rpb;
    int nk4 = astride >> 2;
    for (int i = rstart; i < NN; i += rstride) {
        const float4* a4 = (const float4*)(A + (size_t)i * astride);
        float dot = 0.0f;
        for (int kk = 0; kk < nk4; kk++) {
            float4 av = a4[kk];
            int kb = kk * 4;
            dot += av.x * Wsh[(kb + 0) * dout + c];
            dot += av.y * Wsh[(kb + 1) * dout + c];
            dot += av.z * Wsh[(kb + 2) * dout + c];
            dot += av.w * Wsh[(kb + 3) * dout + c];
        }
        float d = g_dis[i];
        float h = fmaxf(d * dot * scale + off, 0.0f);
        if (to_bf16) g_Pb[(size_t)i * dout + c] = __float2bfloat16(h * d);
        else g_Y[(size_t)i * dout + c] = h;
    }
}

// ---------------- pooling + FC ----------------
__global__ void pool_kernel() {
    int idx = blockIdx.x * blockDim.x + threadIdx.x;
    if (idx >= NN * 16) return;
    int i = idx >> 4;
    int b = g_batch[i];
    float4 v = ((const float4*)g_Y)[idx];
    float* dst = g_pool + (size_t)b * 64 + (idx & 15) * 4;
    unsigned long long p = (unsigned long long)__cvta_generic_to_global(dst);
    asm volatile("red.global.add.v4.f32 [%0], {%1,%2,%3,%4};"
                 :: "l"(p), "f"(v.x), "f"(v.y), "f"(v.z), "f"(v.w) : "memory");
    if ((idx & 15) == 0) atomicAdd(&g_cnt[b], 1.0f);
}

__global__ void fc_kernel(const float* __restrict__ fcW, const float* __restrict__ fcb,
                          float* __restrict__ out) {
    int t = blockIdx.x * blockDim.x + threadIdx.x;
    if (t >= BB * 10) return;
    int b = t / 10;
    int k = t % 10;
    float cnt = fmaxf(g_cnt[b], 1.0f);
    float s = 0.0f;
    for (int j = 0; j < 64; j++) s += g_pool[b * 64 + j] * fcW[j * 10 + k];
    out[t] = s / cnt + fcb[k];
}

extern "C" void kernel_launch(void* const* d_in, const int* in_sizes, int n_in,
                              void* d_out, int out_size) {
    const float* x     = (const float*)d_in[0];
    const void*  ei    = d_in[1];
    const void*  batch = d_in[2];
    const float* W1 = (const float*)d_in[3];
    const float* b1 = (const float*)d_in[4];
    const float* g1 = (const float*)d_in[5];
    const float* be1 = (const float*)d_in[6];
    const float* W2 = (const float*)d_in[7];
    const float* b2 = (const float*)d_in[8];
    const float* g2 = (const float*)d_in[9];
    const float* be2 = (const float*)d_in[10];
    const float* W3 = (const float*)d_in[11];
    const float* b3 = (const float*)d_in[12];
    const float* g3 = (const float*)d_in[13];
    const float* be3 = (const float*)d_in[14];
    const float* fcW = (const float*)d_in[15];
    const float* fcb = (const float*)d_in[16];
    float* out = (float*)d_out;

    float* Ap;
    int* degp;
    cudaGetSymbolAddress((void**)&Ap, g_A);
    cudaGetSymbolAddress((void**)&degp, g_degi);

    // ---- CSR build ----
    cudaMemsetAsync(degp, 0, NN * sizeof(int));
    hist_kernel<<<(EE + 255) / 256, 256>>>(ei);
    scan1_kernel<<<NBLK, 256>>>(batch);
    scan2_kernel<<<1, 128>>>();
    scan3_kernel<<<NBLK, 256>>>();                               // launch 3 (profiled)
    fillprep_kernel<<<(EE + 255) / 256, 256>>>(ei, x);

    // ---- layer 1 (3->16) ----
    gather1_kernel<<<(NN + 255) / 256, 256>>>();
    mom3_kernel<<<128, 256>>>();
    solve_kernel<<<1, 64, 3 * 16 * sizeof(float)>>>(W1, b1, g1, be1, M1OFF, 3, 16);
    fused_out_kernel<<<1024, 256, 4 * 16 * sizeof(float)>>>(Ap, W1, 3, 4, 16, 4, 1);

    // ---- layer 2 (16->32) ----
    gather_bf16_kernel<16><<<(NN * 2 + 255) / 256, 256>>>();
    mom_warp_kernel<16, M2OFF><<<128, 256>>>();
    solve_kernel<<<1, 64, 16 * 32 * sizeof(float)>>>(W2, b2, g2, be2, M2OFF, 16, 32);
    fused_out_kernel<<<1024, 256, 16 * 32 * sizeof(float)>>>(Ap, W2, 16, 16, 32, 5, 1);

    // ---- layer 3 (32->64) ----
    gather_bf16_kernel<32><<<(NN * 4 + 255) / 256, 256>>>();
    mom_warp_kernel<32, M3OFF><<<128, 256>>>();
    solve_kernel<<<1, 64, 32 * 64 * sizeof(float)>>>(W3, b3, g3, be3, M3OFF, 32, 64);
    fused_out_kernel<<<1024, 256, 32 * 64 * sizeof(float)>>>(Ap, W3, 32, 32, 64, 6, 0);

    // ---- pooling + FC ----
    pool_kernel<<<(NN * 16 + 255) / 256, 256>>>();
    fc_kernel<<<(BB * 10 + 255) / 256, 256>>>(fcW, fcb, out);
}

// round 10
// speedup vs baseline: 1.4192x; 1.2869x over previous
#include <cuda_runtime.h>
#include <cuda_bf16.h>

#define NN 100000
#define EE 1600000
#define BB 64
#define BNEPS 1e-5f
#define NBLK ((NN + 1023) / 1024)

// g_M layout per layer: M1[din], then M2 rows padded to (din+1)
#define M1OFF 0
#define M2OFF 16
#define M3OFF 304
#define MTOT 1392

// ---------------- scratch ----------------
__device__ __align__(16) float g_P[(size_t)NN * 4];
__device__ __align__(16) __nv_bfloat16 g_Pb[(size_t)NN * 32];
__device__ __align__(16) float g_A[(size_t)NN * 32];
__device__ __align__(16) int g_degi[NN];
__device__ int g_rowptr[NN + 1];
__device__ int g_cursor[NN];
__device__ int g_src[EE];
__device__ int g_batch[NN];
__device__ float g_dis[NN];
__device__ float g_stats[128];
__device__ float g_M[MTOT];
__device__ int g_bsum[NBLK];
__device__ int g_boff[NBLK];
__device__ __align__(16) float g_pool[BB * 64];
__device__ float g_cnt[BB];
__device__ int g_flag;
__device__ int g_done0;
__device__ int g_d1;
__device__ int g_d2;
__device__ int g_d3;
__device__ int g_d4;

__device__ __forceinline__ int detect_e64(const void* ei) {
    const long long* p = (const long long*)ei;
    int ok = 1;
    for (int i = 0; i < 64; i++) {
        long long v = p[i];
        if (v < 0 || v >= NN) ok = 0;
    }
    return ok;
}

// ---------------- BN solve from moments (device helper) ----------------
__device__ __forceinline__ void solve_body(const float* __restrict__ W,
                                           const float* __restrict__ bias,
                                           const float* __restrict__ gam,
                                           const float* __restrict__ bet,
                                           int moff, int din, int dout, int t) {
    if (t >= dout) return;
    float m1w = 0.0f;
    for (int k = 0; k < din; k++) m1w += g_M[moff + k] * W[k * dout + t];
    float q = 0.0f;
    for (int j = 0; j < din; j++) {
        float wj = W[j * dout + t];
        const float* mrow = &g_M[moff + din + j * (din + 1)];
        for (int k = 0; k < din; k++) q += wj * mrow[k] * W[k * dout + t];
    }
    float bc = bias[t];
    const float inv_n = 1.0f / NN;
    float mu  = m1w * inv_n + bc;
    float ex2 = q * inv_n + 2.0f * bc * m1w * inv_n + bc * bc;
    float var = ex2 - mu * mu;
    float scale = gam[t] * rsqrtf(var + BNEPS);
    g_stats[t] = scale;
    g_stats[64 + t] = (bc - mu) * scale + bet[t];
}

// ---------------- hist (degree) + zero pool/cnt/M in block 0 ----------------
__global__ void hist_kernel(const void* ei) {
    __shared__ int s64;
    if (threadIdx.x == 0) s64 = detect_e64(ei);
    __syncthreads();
    if (blockIdx.x == 0) {
        int t = threadIdx.x;
        for (int u = t; u < BB * 64; u += 256) g_pool[u] = 0.0f;
        if (t < BB) g_cnt[t] = 0.0f;
        for (int u = t; u < MTOT; u += 256) g_M[u] = 0.0f;
    }
    int e = blockIdx.x * blockDim.x + threadIdx.x;
    if (e >= EE) return;
    int c = s64 ? (int)((const long long*)ei)[EE + e] : ((const int*)ei)[EE + e];
    atomicAdd(&g_degi[c], 1);
}

// ---------------- scan phase 1 (+ batch decode + per-batch counts) ----------------
__global__ void scan1_kernel(const void* batch) {
    __shared__ int s[256];
    __shared__ int s64b;
    __shared__ int ch[BB];
    int t = threadIdx.x;
    if (t == 0) {
        const long long* q = (const long long*)batch;
        int okb = 1;
        for (int i = 0; i < 32; i++) {
            long long v = q[NN / 4 + i];
            if (v < 0 || v >= BB) okb = 0;
        }
        s64b = okb;
    }
    if (t < BB) ch[t] = 0;
    int base = blockIdx.x * 1024 + t * 4;
    int sum = 0;
    if (base + 3 < NN) {
        int4 d = *(const int4*)&g_degi[base];
        sum = d.x + d.y + d.z + d.w;
    } else {
        for (int u = 0; u < 4; u++) if (base + u < NN) sum += g_degi[base + u];
    }
    s[t] = sum;
    __syncthreads();
    for (int off = 128; off > 0; off >>= 1) {
        if (t < off) s[t] += s[t + off];
        __syncthreads();
    }
    if (t == 0) g_bsum[blockIdx.x] = s[0];
    int nt = gridDim.x * blockDim.x;
    int b64 = s64b;
    for (int i = blockIdx.x * blockDim.x + t; i < NN; i += nt) {
        int b = b64 ? (int)((const long long*)batch)[i] : ((const int*)batch)[i];
        g_batch[i] = b;
        atomicAdd(&ch[b], 1);
    }
    __syncthreads();
    if (t < BB && ch[t]) atomicAdd(&g_cnt[t], (float)ch[t]);
}

// ---------------- merged scan2+scan3 (spin; NBLK=98 blocks co-resident) ----------------
__global__ void scan23_kernel() {
    int t = threadIdx.x;
    int bid = blockIdx.x;
    __shared__ int s2[128];
    if (bid == 0) {
        int v = 0;
        if (t < 128) { v = (t < NBLK) ? g_bsum[t] : 0; s2[t] = v; }
        __syncthreads();
        for (int off = 1; off < 128; off <<= 1) {
            int u = (t < 128 && t >= off) ? s2[t - off] : 0;
            __syncthreads();
            if (t < 128) s2[t] += u;
            __syncthreads();
        }
        if (t < NBLK) g_boff[t] = s2[t] - v;
        if (t == 127) g_rowptr[NN] = s2[127];
        __threadfence();
        __syncthreads();
        if (t == 0) g_flag = 1;
    } else {
        if (t == 0) { while (((volatile int*)&g_flag)[0] == 0) {} }
        __syncthreads();
    }
    __shared__ int s3[256];
    int base = bid * 1024 + t * 4;
    int d0 = 0, d1 = 0, d2 = 0, d3 = 0;
    if (base + 3 < NN) {
        int4 d = *(const int4*)&g_degi[base];
        d0 = d.x; d1 = d.y; d2 = d.z; d3 = d.w;
    } else {
        if (base + 0 < NN) d0 = g_degi[base + 0];
        if (base + 1 < NN) d1 = g_degi[base + 1];
        if (base + 2 < NN) d2 = g_degi[base + 2];
        if (base + 3 < NN) d3 = g_degi[base + 3];
    }
    int tsum = d0 + d1 + d2 + d3;
    s3[t] = tsum;
    __syncthreads();
    for (int off = 1; off < 256; off <<= 1) {
        int u = (t >= off) ? s3[t - off] : 0;
        __syncthreads();
        s3[t] += u;
        __syncthreads();
    }
    int off = g_boff[bid] + s3[t] - tsum;
    int pre[4] = {off, off + d0, off + d0 + d1, off + d0 + d1 + d2};
    int dd[4] = {d0, d1, d2, d3};
    for (int u = 0; u < 4; u++) {
        int idx = base + u;
        if (idx < NN) {
            g_rowptr[idx] = pre[u];
            g_cursor[idx] = pre[u];
            g_dis[idx] = rsqrtf((float)(dd[u] + 1));
        }
    }
    __syncthreads();
    if (t == 0) {
        int d = atomicAdd(&g_done0, 1);
        if (d == (int)gridDim.x - 1) { g_done0 = 0; g_flag = 0; __threadfence(); }
    }
}

// ---------------- fill CSR + prep layer-1 messages ----------------
__global__ void fillprep_kernel(const void* ei, const float* __restrict__ x) {
    __shared__ int s64;
    if (threadIdx.x == 0) s64 = detect_e64(ei);
    __syncthreads();
    int e = blockIdx.x * blockDim.x + threadIdx.x;
    if (e < EE) {
        int r, c;
        if (s64) {
            const long long* p = (const long long*)ei;
            r = (int)p[e]; c = (int)p[EE + e];
        } else {
            const int* p = (const int*)ei;
            r = p[e]; c = p[EE + e];
        }
        int pos = atomicAdd(&g_cursor[c], 1);
        g_src[pos] = r;
    }
    if (e < NN) {
        float d = g_dis[e];
        ((float4*)g_P)[e] = make_float4(x[3 * e] * d, x[3 * e + 1] * d, x[3 * e + 2] * d, 0.0f);
    }
}

// ---------------- layer-1 gather + inline moments + last-block BN solve ----------------
__global__ void gather1m_kernel(const float* __restrict__ W, const float* __restrict__ bias,
                                const float* __restrict__ gam, const float* __restrict__ bet) {
    __shared__ int last;
    int t = threadIdx.x;
    int i = blockIdx.x * blockDim.x + t;
    float4 acc = make_float4(0, 0, 0, 0);
    float d = 0.0f;
    if (i < NN) {
        const float4* __restrict__ P4 = (const float4*)g_P;
        acc = P4[i];
        int s = g_rowptr[i], e = g_rowptr[i + 1];
        int j = s;
        for (; j + 4 <= e; j += 4) {
            int r0 = g_src[j], r1 = g_src[j + 1], r2 = g_src[j + 2], r3 = g_src[j + 3];
            float4 v0 = P4[r0];
            float4 v1 = P4[r1];
            float4 v2 = P4[r2];
            float4 v3 = P4[r3];
            acc.x += (v0.x + v1.x) + (v2.x + v3.x);
            acc.y += (v0.y + v1.y) + (v2.y + v3.y);
            acc.z += (v0.z + v1.z) + (v2.z + v3.z);
            acc.w += (v0.w + v1.w) + (v2.w + v3.w);
        }
        for (; j < e; j++) {
            float4 v = P4[g_src[j]];
            acc.x += v.x; acc.y += v.y; acc.z += v.z; acc.w += v.w;
        }
        ((float4*)g_A)[i] = acc;
        d = g_dis[i];
    }
    // inline moments (scaled by dis)
    float s0 = acc.x * d, s1 = acc.y * d, s2 = acc.z * d;
    float m[12];
    m[0] = s0; m[1] = s1; m[2] = s2;
    m[3] = s0 * s0; m[4] = s0 * s1; m[5] = s0 * s2;
    m[6] = s1 * s0; m[7] = s1 * s1; m[8] = s1 * s2;
    m[9] = s2 * s0; m[10] = s2 * s1; m[11] = s2 * s2;
#pragma unroll
    for (int u = 0; u < 12; u++)
        for (int o = 16; o > 0; o >>= 1)
            m[u] += __shfl_down_sync(0xffffffffu, m[u], o);
    if ((t & 31) == 0) {
#pragma unroll
        for (int u = 0; u < 3; u++) atomicAdd(&g_M[M1OFF + u], m[u]);
#pragma unroll
        for (int u = 0; u < 9; u++)
            atomicAdd(&g_M[M1OFF + 3 + (u / 3) * 4 + (u % 3)], m[3 + u]);
    }
    __threadfence();
    __syncthreads();
    if (t == 0) last = (atomicAdd(&g_d1, 1) == (int)gridDim.x - 1);
    __syncthreads();
    if (last) {
        if (t == 0) g_d1 = 0;
        __threadfence();
        solve_body(W, bias, gam, bet, M1OFF, 3, 16, t);
    }
}

// ---------------- bf16 gather (CH channels, 8 per thread) ----------------
template <int CH>
__global__ void gather_bf16_kernel() {
    constexpr int TPN = CH / 8;
    int idx = blockIdx.x * blockDim.x + threadIdx.x;
    if (idx >= NN * TPN) return;
    int i = idx / TPN;
    int sub = idx % TPN;
    const uint4* __restrict__ Pb = (const uint4*)g_Pb;
    float acc[8];
    {
        uint4 v = Pb[(size_t)i * TPN + sub];
        const __nv_bfloat162* h = (const __nv_bfloat162*)&v;
#pragma unroll
        for (int u = 0; u < 4; u++) {
            float2 f = __bfloat1622float2(h[u]);
            acc[2 * u] = f.x; acc[2 * u + 1] = f.y;
        }
    }
    int s = g_rowptr[i], e = g_rowptr[i + 1];
    int j = s;
    for (; j + 4 <= e; j += 4) {
        int r0 = g_src[j], r1 = g_src[j + 1], r2 = g_src[j + 2], r3 = g_src[j + 3];
        uint4 v0 = Pb[(size_t)r0 * TPN + sub];
        uint4 v1 = Pb[(size_t)r1 * TPN + sub];
        uint4 v2 = Pb[(size_t)r2 * TPN + sub];
        uint4 v3 = Pb[(size_t)r3 * TPN + sub];
        const __nv_bfloat162* h0 = (const __nv_bfloat162*)&v0;
        const __nv_bfloat162* h1 = (const __nv_bfloat162*)&v1;
        const __nv_bfloat162* h2 = (const __nv_bfloat162*)&v2;
        const __nv_bfloat162* h3 = (const __nv_bfloat162*)&v3;
#pragma unroll
        for (int u = 0; u < 4; u++) {
            float2 f0 = __bfloat1622float2(h0[u]);
            float2 f1 = __bfloat1622float2(h1[u]);
            float2 f2 = __bfloat1622float2(h2[u]);
            float2 f3 = __bfloat1622float2(h3[u]);
            acc[2 * u]     += (f0.x + f1.x) + (f2.x + f3.x);
            acc[2 * u + 1] += (f0.y + f1.y) + (f2.y + f3.y);
        }
    }
    for (; j < e; j++) {
        uint4 v = Pb[(size_t)g_src[j] * TPN + sub];
        const __nv_bfloat162* h = (const __nv_bfloat162*)&v;
#pragma unroll
        for (int u = 0; u < 4; u++) {
            float2 f = __bfloat1622float2(h[u]);
            acc[2 * u] += f.x; acc[2 * u + 1] += f.y;
        }
    }
    float4* Ao = (float4*)(g_A + (size_t)i * CH + sub * 8);
    Ao[0] = make_float4(acc[0], acc[1], acc[2], acc[3]);
    Ao[1] = make_float4(acc[4], acc[5], acc[6], acc[7]);
}

// ---------------- moments din=16/32 + last-block BN solve ----------------
template <int DIN, int MOFF, int DOUT>
__global__ void mom_warp_kernel(const float* __restrict__ W, const float* __restrict__ bias,
                                const float* __restrict__ gam, const float* __restrict__ bet,
                                int* done) {
    constexpr int RPW = 32 / DIN;
    constexpr int NIT = DIN + DIN * (DIN + 1);
    __shared__ float Msh[NIT];
    __shared__ int last;
    int t = threadIdx.x;
    for (int u = t; u < NIT; u += 256) Msh[u] = 0.0f;
    __syncthreads();
    int lane = t & 31, w = t >> 5;
    int gw = blockIdx.x * 8 + w;
    int sub = lane / DIN;
    int ch = lane % DIN;
    float acc1 = 0.0f;
    float acc2[DIN];
#pragma unroll
    for (int k = 0; k < DIN; k++) acc2[k] = 0.0f;
    int stride = gridDim.x * 8 * RPW;
    for (int r0 = gw * RPW; r0 < NN; r0 += stride) {
        int r = r0 + sub;
        float s = g_A[(size_t)r * DIN + ch] * g_dis[r];
        acc1 += s;
#pragma unroll
        for (int k = 0; k < DIN; k++)
            acc2[k] += s * __shfl_sync(0xffffffffu, s, k, DIN);
    }
    atomicAdd(&Msh[ch], acc1);
#pragma unroll
    for (int k = 0; k < DIN; k++)
        atomicAdd(&Msh[DIN + ch * (DIN + 1) + k], acc2[k]);
    __syncthreads();
    for (int u = t; u < NIT; u += 256) atomicAdd(&g_M[MOFF + u], Msh[u]);
    __threadfence();
    __syncthreads();
    if (t == 0) last = (atomicAdd(done, 1) == (int)gridDim.x - 1);
    __syncthreads();
    if (last) {
        if (t == 0) *done = 0;
        __threadfence();
        solve_body(W, bias, gam, bet, MOFF, DIN, DOUT, t);
    }
}

// ---------------- fused (layers 1-2): h = relu(bn(dis*(A@W)+b)) -> bf16 P ----------------
__global__ void fused_out_kernel(const float* __restrict__ A, const float* __restrict__ W,
                                 int din, int astride, int dout, int ld) {
    extern __shared__ float Wsh[];
    for (int u = threadIdx.x; u < astride * dout; u += blockDim.x)
        Wsh[u] = (u < din * dout) ? W[u] : 0.0f;
    __syncthreads();
    int t = threadIdx.x;
    int c = t & (dout - 1);
    float scale = g_stats[c];
    float off = g_stats[64 + c];
    int rpb = 256 >> ld;
    int rstart = blockIdx.x * rpb + (t >> ld);
    int rstride = gridDim.x * rpb;
    int nk4 = astride >> 2;
    for (int i = rstart; i < NN; i += rstride) {
        const float4* a4 = (const float4*)(A + (size_t)i * astride);
        float dot = 0.0f;
        for (int kk = 0; kk < nk4; kk++) {
            float4 av = a4[kk];
            int kb = kk * 4;
            dot += av.x * Wsh[(kb + 0) * dout + c];
            dot += av.y * Wsh[(kb + 1) * dout + c];
            dot += av.z * Wsh[(kb + 2) * dout + c];
            dot += av.w * Wsh[(kb + 3) * dout + c];
        }
        float d = g_dis[i];
        float h = fmaxf(d * dot * scale + off, 0.0f);
        g_Pb[(size_t)i * dout + c] = __float2bfloat16(h * d);
    }
}

// ---------------- layer 3 fused: bn+relu -> smem pool -> RED -> last-block FC ----------------
__global__ void fused3_pool_kernel(const float* __restrict__ A, const float* __restrict__ W,
                                   const float* __restrict__ fcW, const float* __restrict__ fcb,
                                   float* __restrict__ out) {
    __shared__ float Wsh[32 * 64];
    __shared__ float pool[BB * 64];
    __shared__ int last;
    int t = threadIdx.x;
    for (int u = t; u < 32 * 64; u += 256) Wsh[u] = W[u];
    for (int u = t; u < BB * 64; u += 256) pool[u] = 0.0f;
    __syncthreads();
    int c = t & 63;
    float scale = g_stats[c];
    float off = g_stats[64 + c];
    int rpb = 4;  // 256/64
    int rstart = blockIdx.x * rpb + (t >> 6);
    int rstride = gridDim.x * rpb;
    for (int i = rstart; i < NN; i += rstride) {
        const float4* a4 = (const float4*)(A + (size_t)i * 32);
        float dot = 0.0f;
#pragma unroll
        for (int kk = 0; kk < 8; kk++) {
            float4 av = a4[kk];
            int kb = kk * 4;
            dot += av.x * Wsh[(kb + 0) * 64 + c];
            dot += av.y * Wsh[(kb + 1) * 64 + c];
            dot += av.z * Wsh[(kb + 2) * 64 + c];
            dot += av.w * Wsh[(kb + 3) * 64 + c];
        }
        float d = g_dis[i];
        float h = fmaxf(d * dot * scale + off, 0.0f);
        atomicAdd(&pool[g_batch[i] * 64 + c], h);
    }
    __syncthreads();
    for (int u = t; u < BB * 16; u += 256) {
        float4 v = ((const float4*)pool)[u];
        float* dst = g_pool + u * 4;
        unsigned long long p = (unsigned long long)__cvta_generic_to_global(dst);
        asm volatile("red.global.add.v4.f32 [%0], {%1,%2,%3,%4};"
                     :: "l"(p), "f"(v.x), "f"(v.y), "f"(v.z), "f"(v.w) : "memory");
    }
    __threadfence();
    __syncthreads();
    if (t == 0) last = (atomicAdd(&g_d4, 1) == (int)gridDim.x - 1);
    __syncthreads();
    if (last) {
        if (t == 0) g_d4 = 0;
        __threadfence();
        for (int u = t; u < BB * 10; u += 256) {
            int b = u / 10;
            int k = u % 10;
            float cnt = fmaxf(g_cnt[b], 1.0f);
            float s = 0.0f;
            for (int j = 0; j < 64; j++) s += g_pool[b * 64 + j] * fcW[j * 10 + k];
            out[u] = s / cnt + fcb[k];
        }
    }
}

extern "C" void kernel_launch(void* const* d_in, const int* in_sizes, int n_in,
                              void* d_out, int out_size) {
    const float* x     = (const float*)d_in[0];
    const void*  ei    = d_in[1];
    const void*  batch = d_in[2];
    const float* W1 = (const float*)d_in[3];
    const float* b1 = (const float*)d_in[4];
    const float* g1 = (const float*)d_in[5];
    const float* be1 = (const float*)d_in[6];
    const float* W2 = (const float*)d_in[7];
    const float* b2 = (const float*)d_in[8];
    const float* g2 = (const float*)d_in[9];
    const float* be2 = (const float*)d_in[10];
    const float* W3 = (const float*)d_in[11];
    const float* b3 = (const float*)d_in[12];
    const float* g3 = (const float*)d_in[13];
    const float* be3 = (const float*)d_in[14];
    const float* fcW = (const float*)d_in[15];
    const float* fcb = (const float*)d_in[16];
    float* out = (float*)d_out;

    float* Ap;
    int *degp, *d2p, *d3p;
    cudaGetSymbolAddress((void**)&Ap, g_A);
    cudaGetSymbolAddress((void**)&degp, g_degi);
    cudaGetSymbolAddress((void**)&d2p, g_d2);
    cudaGetSymbolAddress((void**)&d3p, g_d3);

    // ---- CSR build ----
    cudaMemsetAsync(degp, 0, NN * sizeof(int));
    hist_kernel<<<(EE + 255) / 256, 256>>>(ei);
    scan1_kernel<<<NBLK, 256>>>(batch);
    scan23_kernel<<<NBLK, 256>>>();
    fillprep_kernel<<<(EE + 255) / 256, 256>>>(ei, x);

    // ---- layer 1 (3->16) ----
    gather1m_kernel<<<(NN + 255) / 256, 256>>>(W1, b1, g1, be1);
    fused_out_kernel<<<1024, 256, 4 * 16 * sizeof(float)>>>(Ap, W1, 3, 4, 16, 4);

    // ---- layer 2 (16->32) ----
    gather_bf16_kernel<16><<<(NN * 2 + 255) / 256, 256>>>();
    mom_warp_kernel<16, M2OFF, 32><<<128, 256>>>(W2, b2, g2, be2, d2p);
    fused_out_kernel<<<1024, 256, 16 * 32 * sizeof(float)>>>(Ap, W2, 16, 16, 32, 5);

    // ---- layer 3 (32->64) ----
    gather_bf16_kernel<32><<<(NN * 4 + 255) / 256, 256>>>();
    mom_warp_kernel<32, M3OFF, 64><<<128, 256>>>(W3, b3, g3, be3, d3p);
    fused3_pool_kernel<<<592, 256>>>(Ap, W3, fcW, fcb, out);
}

// round 12
// speedup vs baseline: 1.6802x; 1.1840x over previous
#include <cuda_runtime.h>
#include <cuda_bf16.h>

#define NN 100000
#define EE 1600000
#define BB 64
#define BNEPS 1e-5f

// g_M layout per layer: M1[din], then M2 rows padded to (din+1)
#define M1OFF 0
#define M2OFF 16
#define M3OFF 304
#define MTOT 1392

// ---------------- scratch ----------------
__device__ __align__(16) float g_P[(size_t)NN * 4];
__device__ __align__(16) __nv_bfloat16 g_Pb[(size_t)NN * 32];
__device__ __align__(16) float g_A[(size_t)NN * 32];
__device__ __align__(16) int g_degi[NN];
__device__ int g_rowptr[NN + 1];
__device__ int g_cursor[NN];
__device__ int g_src[EE];
__device__ int g_batch[NN];
__device__ float g_dis[NN];
__device__ float g_stats[128];
__device__ float g_M[MTOT];
__device__ int g_bsum[98];
__device__ int g_boff[98];
__device__ __align__(16) float g_pool[BB * 64];
__device__ int g_cnti[BB];
// sync state (all must be 0 at entry of every replay; self-resetting)
__device__ int s_cA, s_fA, s_cB, s_fB, s_fC, s_cD, s_fD, s_cF;
__device__ int l1_c, l1_f, l1_c2;
__device__ int m2_c, m2_f, m2_c2;
__device__ int m3_c, m3_f, m3_c2;

__device__ __forceinline__ int detect_e64(const void* ei) {
    const long long* p = (const long long*)ei;
    int ok = 1;
    for (int i = 0; i < 64; i++) {
        long long v = p[i];
        if (v < 0 || v >= NN) ok = 0;
    }
    return ok;
}

// block-wide arrive + wait on a global counter/flag pair
#define ARRIVE_AND_WAIT(cnt, flag) do {                                        \
    __threadfence(); __syncthreads();                                          \
    if (threadIdx.x == 0) {                                                    \
        if (atomicAdd(&(cnt), 1) == (int)gridDim.x - 1)                        \
            *((volatile int*)&(flag)) = 1;                                     \
        while (*((volatile int*)&(flag)) == 0) {}                              \
    }                                                                          \
    __syncthreads(); __threadfence();                                          \
} while (0)

// ---------------- BN solve from moments ----------------
__device__ __forceinline__ void solve_body(const float* __restrict__ W,
                                           const float* __restrict__ bias,
                                           const float* __restrict__ gam,
                                           const float* __restrict__ bet,
                                           int moff, int din, int dout, int t) {
    if (t >= dout) return;
    float m1w = 0.0f;
    for (int k = 0; k < din; k++) m1w += g_M[moff + k] * W[k * dout + t];
    float q = 0.0f;
    for (int j = 0; j < din; j++) {
        float wj = W[j * dout + t];
        const float* mrow = &g_M[moff + din + j * (din + 1)];
        for (int k = 0; k < din; k++) q += wj * mrow[k] * W[k * dout + t];
    }
    float bc = bias[t];
    const float inv_n = 1.0f / NN;
    float mu  = m1w * inv_n + bc;
    float ex2 = q * inv_n + 2.0f * bc * m1w * inv_n + bc * bc;
    float var = ex2 - mu * mu;
    float scale = gam[t] * rsqrtf(var + BNEPS);
    g_stats[t] = scale;
    g_stats[64 + t] = (bc - mu) * scale + bet[t];
}

// ---------------- persistent CSR build: hist -> scan -> fill ----------------
__global__ void __launch_bounds__(256, 4) csr_kernel(const void* ei, const void* batch,
                                                     const float* __restrict__ x) {
    int t = threadIdx.x, bid = blockIdx.x, G = gridDim.x;
    __shared__ int s64, s64b;
    __shared__ int ch[BB];
    if (t == 0) s64 = detect_e64(ei);
    if (t == 1) {
        const long long* q = (const long long*)batch;
        int okb = 1;
        for (int i2 = 0; i2 < 32; i2++) {
            long long v = q[NN / 4 + i2];
            if (v < 0 || v >= BB) okb = 0;
        }
        s64b = okb;
    }
    if (t < BB) ch[t] = 0;
    __syncthreads();
    int e64 = s64, b64 = s64b;
    // ---- phase 1: degree hist + batch decode ----
    for (int e = bid * 256 + t; e < EE; e += G * 256) {
        int c = e64 ? (int)((const long long*)ei)[EE + e] : ((const int*)ei)[EE + e];
        atomicAdd(&g_degi[c], 1);
    }
    for (int i = bid * 256 + t; i < NN; i += G * 256) {
        int b = b64 ? (int)((const long long*)batch)[i] : ((const int*)batch)[i];
        g_batch[i] = b;
        atomicAdd(&ch[b], 1);
    }
    __syncthreads();
    if (t < BB && ch[t]) atomicAdd(&g_cnti[t], ch[t]);
    ARRIVE_AND_WAIT(s_cA, s_fA);
    // ---- phase 2: per-chunk sums (blocks 0..97, 1024 elems each) ----
    __shared__ int sh1[256];
    if (bid < 98) {
        int base = bid * 1024 + t * 4;
        int sum = 0;
        if (base + 3 < NN) {
            int4 d = *(const int4*)&g_degi[base];
            sum = d.x + d.y + d.z + d.w;
        } else {
            for (int u = 0; u < 4; u++) if (base + u < NN) sum += g_degi[base + u];
        }
        sh1[t] = sum;
        __syncthreads();
        for (int off = 128; off > 0; off >>= 1) {
            if (t < off) sh1[t] += sh1[t + off];
            __syncthreads();
        }
        if (t == 0) g_bsum[bid] = sh1[0];
    }
    ARRIVE_AND_WAIT(s_cB, s_fB);
    // ---- phase 3: block 0 scans the 98 sums ----
    if (bid == 0) {
        __shared__ int s2[128];
        int v = 0;
        if (t < 128) { v = (t < 98) ? g_bsum[t] : 0; s2[t] = v; }
        __syncthreads();
        for (int off = 1; off < 128; off <<= 1) {
            int u = (t < 128 && t >= off) ? s2[t - off] : 0;
            __syncthreads();
            if (t < 128) s2[t] += u;
            __syncthreads();
        }
        if (t < 98) g_boff[t] = s2[t] - v;
        if (t == 127) g_rowptr[NN] = s2[127];
        __threadfence(); __syncthreads();
        if (t == 0) *((volatile int*)&s_fC) = 1;
    }
    if (t == 0) { while (*((volatile int*)&s_fC) == 0) {} }
    __syncthreads(); __threadfence();
    // ---- phase 4: rowptr/cursor/dis + re-zero degi (blocks 0..97) ----
    __shared__ int sh3[256];
    if (bid < 98) {
        int base = bid * 1024 + t * 4;
        int d0 = 0, d1 = 0, d2 = 0, d3 = 0;
        if (base + 3 < NN) {
            int4 d = *(const int4*)&g_degi[base];
            d0 = d.x; d1 = d.y; d2 = d.z; d3 = d.w;
            *(int4*)&g_degi[base] = make_int4(0, 0, 0, 0);
        } else {
            if (base + 0 < NN) { d0 = g_degi[base + 0]; g_degi[base + 0] = 0; }
            if (base + 1 < NN) { d1 = g_degi[base + 1]; g_degi[base + 1] = 0; }
            if (base + 2 < NN) { d2 = g_degi[base + 2]; g_degi[base + 2] = 0; }
            if (base + 3 < NN) { d3 = g_degi[base + 3]; g_degi[base + 3] = 0; }
        }
        int tsum = d0 + d1 + d2 + d3;
        sh3[t] = tsum;
        __syncthreads();
        for (int off = 1; off < 256; off <<= 1) {
            int u = (t >= off) ? sh3[t - off] : 0;
            __syncthreads();
            sh3[t] += u;
            __syncthreads();
        }
        int off = g_boff[bid] + sh3[t] - tsum;
        int pre[4] = {off, off + d0, off + d0 + d1, off + d0 + d1 + d2};
        int dd[4] = {d0, d1, d2, d3};
        for (int u = 0; u < 4; u++) {
            int idx = base + u;
            if (idx < NN) {
                g_rowptr[idx] = pre[u];
                g_cursor[idx] = pre[u];
                g_dis[idx] = rsqrtf((float)(dd[u] + 1));
            }
        }
    }
    ARRIVE_AND_WAIT(s_cD, s_fD);
    // ---- phase 5: fill CSR + prep layer-1 messages ----
    for (int e = bid * 256 + t; e < EE; e += G * 256) {
        int r, c;
        if (e64) {
            const long long* p = (const long long*)ei;
            r = (int)p[e]; c = (int)p[EE + e];
        } else {
            const int* p = (const int*)ei;
            r = p[e]; c = p[EE + e];
        }
        int pos = atomicAdd(&g_cursor[c], 1);
        g_src[pos] = r;
    }
    for (int i = bid * 256 + t; i < NN; i += G * 256) {
        float d = g_dis[i];
        ((float4*)g_P)[i] = make_float4(x[3 * i] * d, x[3 * i + 1] * d, x[3 * i + 2] * d, 0.0f);
    }
    // ---- final: reset sync state (no one waits on s_cF) ----
    __threadfence(); __syncthreads();
    if (t == 0) {
        if (atomicAdd(&s_cF, 1) == G - 1) {
            s_cA = 0; s_fA = 0; s_cB = 0; s_fB = 0; s_fC = 0; s_cD = 0; s_fD = 0; s_cF = 0;
            __threadfence();
        }
    }
}

// ---------------- layer 1: gather + moments + solve + fused output, one kernel ----------------
__global__ void __launch_bounds__(256, 4) layer1_kernel(const float* __restrict__ W,
                                                        const float* __restrict__ bias,
                                                        const float* __restrict__ gam,
                                                        const float* __restrict__ bet) {
    __shared__ float Wsh[48];
    __shared__ int last;
    int t = threadIdx.x;
    if (t < 48) Wsh[t] = W[t];
    int i = blockIdx.x * 256 + t;
    float4 acc = make_float4(0, 0, 0, 0);
    float d = 0.0f;
    if (i < NN) {
        const float4* __restrict__ P4 = (const float4*)g_P;
        acc = P4[i];
        int s = g_rowptr[i], e = g_rowptr[i + 1];
        int j = s;
        for (; j + 4 <= e; j += 4) {
            int r0 = g_src[j], r1 = g_src[j + 1], r2 = g_src[j + 2], r3 = g_src[j + 3];
            float4 v0 = P4[r0];
            float4 v1 = P4[r1];
            float4 v2 = P4[r2];
            float4 v3 = P4[r3];
            acc.x += (v0.x + v1.x) + (v2.x + v3.x);
            acc.y += (v0.y + v1.y) + (v2.y + v3.y);
            acc.z += (v0.z + v1.z) + (v2.z + v3.z);
            acc.w += (v0.w + v1.w) + (v2.w + v3.w);
        }
        for (; j < e; j++) {
            float4 v = P4[g_src[j]];
            acc.x += v.x; acc.y += v.y; acc.z += v.z; acc.w += v.w;
        }
        d = g_dis[i];
    }
    // inline moments (scaled by dis)
    float s0 = acc.x * d, s1 = acc.y * d, s2 = acc.z * d;
    float m[12];
    m[0] = s0; m[1] = s1; m[2] = s2;
    m[3] = s0 * s0; m[4] = s0 * s1; m[5] = s0 * s2;
    m[6] = s1 * s0; m[7] = s1 * s1; m[8] = s1 * s2;
    m[9] = s2 * s0; m[10] = s2 * s1; m[11] = s2 * s2;
#pragma unroll
    for (int u = 0; u < 12; u++)
        for (int o = 16; o > 0; o >>= 1)
            m[u] += __shfl_down_sync(0xffffffffu, m[u], o);
    if ((t & 31) == 0) {
#pragma unroll
        for (int u = 0; u < 3; u++) atomicAdd(&g_M[M1OFF + u], m[u]);
#pragma unroll
        for (int u = 0; u < 9; u++)
            atomicAdd(&g_M[M1OFF + 3 + (u / 3) * 4 + (u % 3)], m[3 + u]);
    }
    __threadfence(); __syncthreads();
    if (t == 0) last = (atomicAdd(&l1_c, 1) == (int)gridDim.x - 1);
    __syncthreads();
    if (last) {
        solve_body(Wsh, bias, gam, bet, M1OFF, 3, 16, t);
        __syncthreads();
        if (t < 16) g_M[M1OFF + t] = 0.0f;   // M1 region = 15 entries, zero 16
        __threadfence(); __syncthreads();
        if (t == 0) *((volatile int*)&l1_f) = 1;
    }
    if (t == 0) { while (*((volatile int*)&l1_f) == 0) {} }
    __syncthreads(); __threadfence();
    // fused output straight from registers
    if (i < NN) {
        float hv[16];
#pragma unroll
        for (int c = 0; c < 16; c++) {
            float dot = acc.x * Wsh[c] + acc.y * Wsh[16 + c] + acc.z * Wsh[32 + c];
            hv[c] = fmaxf(d * dot * g_stats[c] + g_stats[64 + c], 0.0f) * d;
        }
        __nv_bfloat162 pk[8];
#pragma unroll
        for (int u = 0; u < 8; u++) pk[u] = __floats2bfloat162_rn(hv[2 * u], hv[2 * u + 1]);
        uint4* dst = (uint4*)(g_Pb + (size_t)i * 16);
        dst[0] = *(uint4*)&pk[0];
        dst[1] = *(uint4*)&pk[4];
    }
    __syncthreads();
    if (t == 0) {
        if (atomicAdd(&l1_c2, 1) == (int)gridDim.x - 1) {
            l1_c = 0; l1_c2 = 0; l1_f = 0; __threadfence();
        }
    }
}

// ---------------- bf16 gather (unchanged hot loop) ----------------
template <int CH>
__global__ void gather_bf16_kernel() {
    constexpr int TPN = CH / 8;
    int idx = blockIdx.x * blockDim.x + threadIdx.x;
    if (idx >= NN * TPN) return;
    int i = idx / TPN;
    int sub = idx % TPN;
    const uint4* __restrict__ Pb = (const uint4*)g_Pb;
    float acc[8];
    {
        uint4 v = Pb[(size_t)i * TPN + sub];
        const __nv_bfloat162* h = (const __nv_bfloat162*)&v;
#pragma unroll
        for (int u = 0; u < 4; u++) {
            float2 f = __bfloat1622float2(h[u]);
            acc[2 * u] = f.x; acc[2 * u + 1] = f.y;
        }
    }
    int s = g_rowptr[i], e = g_rowptr[i + 1];
    int j = s;
    for (; j + 4 <= e; j += 4) {
        int r0 = g_src[j], r1 = g_src[j + 1], r2 = g_src[j + 2], r3 = g_src[j + 3];
        uint4 v0 = Pb[(size_t)r0 * TPN + sub];
        uint4 v1 = Pb[(size_t)r1 * TPN + sub];
        uint4 v2 = Pb[(size_t)r2 * TPN + sub];
        uint4 v3 = Pb[(size_t)r3 * TPN + sub];
        const __nv_bfloat162* h0 = (const __nv_bfloat162*)&v0;
        const __nv_bfloat162* h1 = (const __nv_bfloat162*)&v1;
        const __nv_bfloat162* h2 = (const __nv_bfloat162*)&v2;
        const __nv_bfloat162* h3 = (const __nv_bfloat162*)&v3;
#pragma unroll
        for (int u = 0; u < 4; u++) {
            float2 f0 = __bfloat1622float2(h0[u]);
            float2 f1 = __bfloat1622float2(h1[u]);
            float2 f2 = __bfloat1622float2(h2[u]);
            float2 f3 = __bfloat1622float2(h3[u]);
            acc[2 * u]     += (f0.x + f1.x) + (f2.x + f3.x);
            acc[2 * u + 1] += (f0.y + f1.y) + (f2.y + f3.y);
        }
    }
    for (; j < e; j++) {
        uint4 v = Pb[(size_t)g_src[j] * TPN + sub];
        const __nv_bfloat162* h = (const __nv_bfloat162*)&v;
#pragma unroll
        for (int u = 0; u < 4; u++) {
            float2 f = __bfloat1622float2(h[u]);
            acc[2 * u] += f.x; acc[2 * u + 1] += f.y;
        }
    }
    float4* Ao = (float4*)(g_A + (size_t)i * CH + sub * 8);
    Ao[0] = make_float4(acc[0], acc[1], acc[2], acc[3]);
    Ao[1] = make_float4(acc[4], acc[5], acc[6], acc[7]);
}

// ---------------- moments phase (device helper) ----------------
template <int DIN, int MOFF>
__device__ __forceinline__ void mom_phase(int t) {
    constexpr int RPW = 32 / DIN;
    constexpr int NIT = DIN + DIN * (DIN + 1);
    __shared__ float Msh[NIT];
    for (int u = t; u < NIT; u += 256) Msh[u] = 0.0f;
    __syncthreads();
    int lane = t & 31, w = t >> 5;
    int gw = blockIdx.x * 8 + w;
    int sub = lane / DIN;
    int ch = lane % DIN;
    float acc1 = 0.0f;
    float acc2[DIN];
#pragma unroll
    for (int k = 0; k < DIN; k++) acc2[k] = 0.0f;
    int stride = gridDim.x * 8 * RPW;
    for (int r0 = gw * RPW; r0 < NN; r0 += stride) {
        int r = r0 + sub;
        float s = g_A[(size_t)r * DIN + ch] * g_dis[r];
        acc1 += s;
#pragma unroll
        for (int k = 0; k < DIN; k++)
            acc2[k] += s * __shfl_sync(0xffffffffu, s, k, DIN);
    }
    atomicAdd(&Msh[ch], acc1);
#pragma unroll
    for (int k = 0; k < DIN; k++)
        atomicAdd(&Msh[DIN + ch * (DIN + 1) + k], acc2[k]);
    __syncthreads();
    for (int u = t; u < NIT; u += 256) atomicAdd(&g_M[MOFF + u], Msh[u]);
}

// ---------------- layer 2: moments + solve + fused output ----------------
__global__ void __launch_bounds__(256, 4) momfused2_kernel(const float* __restrict__ W,
                                                           const float* __restrict__ bias,
                                                           const float* __restrict__ gam,
                                                           const float* __restrict__ bet) {
    __shared__ float Wsh[16 * 32];
    __shared__ int last;
    int t = threadIdx.x;
    for (int u = t; u < 512; u += 256) Wsh[u] = W[u];
    mom_phase<16, M2OFF>(t);
    __threadfence(); __syncthreads();
    if (t == 0) last = (atomicAdd(&m2_c, 1) == (int)gridDim.x - 1);
    __syncthreads();
    if (last) {
        solve_body(Wsh, bias, gam, bet, M2OFF, 16, 32, t);
        __syncthreads();
        for (int u = t; u < 288; u += 256) g_M[M2OFF + u] = 0.0f;
        __threadfence(); __syncthreads();
        if (t == 0) *((volatile int*)&m2_f) = 1;
    }
    if (t == 0) { while (*((volatile int*)&m2_f) == 0) {} }
    __syncthreads(); __threadfence();
    // fused: h = relu(bn(dis*(A@W)+b)) -> bf16 P (dout=32)
    int c = t & 31;
    float scale = g_stats[c], off = g_stats[64 + c];
    int rstart = blockIdx.x * 8 + (t >> 5);
    int rstride = gridDim.x * 8;
    for (int i = rstart; i < NN; i += rstride) {
        const float4* a4 = (const float4*)(g_A + (size_t)i * 16);
        float dot = 0.0f;
#pragma unroll
        for (int kk = 0; kk < 4; kk++) {
            float4 av = a4[kk];
            int kb = kk * 4;
            dot += av.x * Wsh[(kb + 0) * 32 + c];
            dot += av.y * Wsh[(kb + 1) * 32 + c];
            dot += av.z * Wsh[(kb + 2) * 32 + c];
            dot += av.w * Wsh[(kb + 3) * 32 + c];
        }
        float d = g_dis[i];
        float h = fmaxf(d * dot * scale + off, 0.0f);
        g_Pb[(size_t)i * 32 + c] = __float2bfloat16(h * d);
    }
    __syncthreads();
    if (t == 0) {
        if (atomicAdd(&m2_c2, 1) == (int)gridDim.x - 1) {
            m2_c = 0; m2_c2 = 0; m2_f = 0; __threadfence();
        }
    }
}

// ---------------- layer 3: moments + solve + fused bn/relu -> pool -> FC ----------------
__global__ void __launch_bounds__(256, 4) momfused3_kernel(const float* __restrict__ W,
                                                           const float* __restrict__ bias,
                                                           const float* __restrict__ gam,
                                                           const float* __restrict__ bet,
                                                           const float* __restrict__ fcW,
                                                           const float* __restrict__ fcb,
                                                           float* __restrict__ out) {
    __shared__ float Wsh[32 * 64];
    __shared__ float pool[BB * 64];
    __shared__ int last;
    int t = threadIdx.x;
    for (int u = t; u < 2048; u += 256) Wsh[u] = W[u];
    for (int u = t; u < BB * 64; u += 256) pool[u] = 0.0f;
    mom_phase<32, M3OFF>(t);
    __threadfence(); __syncthreads();
    if (t == 0) last = (atomicAdd(&m3_c, 1) == (int)gridDim.x - 1);
    __syncthreads();
    if (last) {
        solve_body(Wsh, bias, gam, bet, M3OFF, 32, 64, t);
        __syncthreads();
        for (int u = t; u < 1088; u += 256) g_M[M3OFF + u] = 0.0f;
        __threadfence(); __syncthreads();
        if (t == 0) *((volatile int*)&m3_f) = 1;
    }
    if (t == 0) { while (*((volatile int*)&m3_f) == 0) {} }
    __syncthreads(); __threadfence();
    // fused bn/relu -> smem pool
    int c = t & 63;
    float scale = g_stats[c], off = g_stats[64 + c];
    int rstart = blockIdx.x * 4 + (t >> 6);
    int rstride = gridDim.x * 4;
    for (int i = rstart; i < NN; i += rstride) {
        const float4* a4 = (const float4*)(g_A + (size_t)i * 32);
        float dot = 0.0f;
#pragma unroll
        for (int kk = 0; kk < 8; kk++) {
            float4 av = a4[kk];
            int kb = kk * 4;
            dot += av.x * Wsh[(kb + 0) * 64 + c];
            dot += av.y * Wsh[(kb + 1) * 64 + c];
            dot += av.z * Wsh[(kb + 2) * 64 + c];
            dot += av.w * Wsh[(kb + 3) * 64 + c];
        }
        float d = g_dis[i];
        float h = fmaxf(d * dot * scale + off, 0.0f);
        atomicAdd(&pool[g_batch[i] * 64 + c], h);
    }
    __syncthreads();
    for (int u = t; u < BB * 16; u += 256) {
        float4 v = ((const float4*)pool)[u];
        float* dst = g_pool + u * 4;
        unsigned long long p = (unsigned long long)__cvta_generic_to_global(dst);
        asm volatile("red.global.add.v4.f32 [%0], {%1,%2,%3,%4};"
                     :: "l"(p), "f"(v.x), "f"(v.y), "f"(v.z), "f"(v.w) : "memory");
    }
    __threadfence(); __syncthreads();
    if (t == 0) last = (atomicAdd(&m3_c2, 1) == (int)gridDim.x - 1);
    __syncthreads();
    if (last) {
        __threadfence();
        for (int u = t; u < BB * 10; u += 256) {
            int b = u / 10;
            int k = u % 10;
            float cnt = fmaxf((float)g_cnti[b], 1.0f);
            float s = 0.0f;
            for (int j = 0; j < 64; j++) s += g_pool[b * 64 + j] * fcW[j * 10 + k];
            out[u] = s / cnt + fcb[k];
        }
        __syncthreads();
        // self-reset accumulators + sync state for next replay
        for (int u = t; u < BB * 64; u += 256) g_pool[u] = 0.0f;
        if (t < BB) g_cnti[t] = 0;
        if (t == 0) { m3_c = 0; m3_c2 = 0; m3_f = 0; }
        __threadfence();
    }
}

extern "C" void kernel_launch(void* const* d_in, const int* in_sizes, int n_in,
                              void* d_out, int out_size) {
    const float* x     = (const float*)d_in[0];
    const void*  ei    = d_in[1];
    const void*  batch = d_in[2];
    const float* W1 = (const float*)d_in[3];
    const float* b1 = (const float*)d_in[4];
    const float* g1 = (const float*)d_in[5];
    const float* be1 = (const float*)d_in[6];
    const float* W2 = (const float*)d_in[7];
    const float* b2 = (const float*)d_in[8];
    const float* g2 = (const float*)d_in[9];
    const float* be2 = (const float*)d_in[10];
    const float* W3 = (const float*)d_in[11];
    const float* b3 = (const float*)d_in[12];
    const float* g3 = (const float*)d_in[13];
    const float* be3 = (const float*)d_in[14];
    const float* fcW = (const float*)d_in[15];
    const float* fcb = (const float*)d_in[16];
    float* out = (float*)d_out;

    csr_kernel<<<592, 256>>>(ei, batch, x);
    layer1_kernel<<<391, 256>>>(W1, b1, g1, be1);
    gather_bf16_kernel<16><<<(NN * 2 + 255) / 256, 256>>>();
    momfused2_kernel<<<592, 256>>>(W2, b2, g2, be2);
    gather_bf16_kernel<32><<<(NN * 4 + 255) / 256, 256>>>();
    momfused3_kernel<<<592, 256>>>(W3, b3, g3, be3, fcW, fcb, out);
}